// round 8
// baseline (speedup 1.0000x reference)
#include <cuda_runtime.h>
#include <math.h>

// Problem constants (fixed for this dataset instance)
#define HQ   16
#define HKV  2
#define DIM  128
#define SCALE 0.08838834764831845f   // 1/sqrt(128)
#define MAXS   1536
#define MAXTC  95
#define NKBLK  24                    // S/64
#define WIN    512
#define KPAD 132                     // K/V row pad: 16B-aligned, conflict-free float4
#define QT   32                      // queries per CTA

// ---------------- device scratch (static, no allocation) ----------------
__device__ float    g_ck [MAXTC * HKV * DIM];
__device__ float    g_cv [MAXTC * HKV * DIM];
__device__ float    g_cmp[MAXS * HQ * DIM];      // compressed-branch output
__device__ unsigned g_sel[HKV * MAXS];           // 24-bit selected-block mask

// =====================================================================
// Kernel A: compressed K/V   ck[t,h,:] = (blk(k)+pek) @ Wk + bk
// grid (ceil(Tc/2), HKV, 4[e-split]), block 512, 2 CTAs/SM
// =====================================================================
__global__ __launch_bounds__(512, 2)
void compress_kernel(const float* __restrict__ k, const float* __restrict__ v,
                     const float* __restrict__ Wk, const float* __restrict__ bk,
                     const float* __restrict__ Wv, const float* __restrict__ bv,
                     const float* __restrict__ pek, const float* __restrict__ pev,
                     int S, int Tc)
{
    extern __shared__ float sm[];
    float* xk  = sm;               // [2][4096]
    float* xv  = sm + 2 * 4096;    // [2][4096]
    float* red = sm + 4 * 4096;    // [2][16seg][2tt][32]

    const int h   = blockIdx.y;
    const int t0  = blockIdx.x * 2;
    const int e0  = blockIdx.z * 32;
    const int tid = threadIdx.x;
    const int seg = tid >> 5;          // 0..15
    const int lane = tid & 31;
    const int e   = e0 + lane;

    for (int tt = 0; tt < 2; ++tt) {
        int t = t0 + tt;
        if (t >= Tc) break;
        // vectorized fill: 4096 floats = 1024 float4
        for (int f = tid; f < 1024; f += 512) {
            int l = f >> 5, d4 = (f & 31) << 2;
            int pos = t * 16 + l;
            const float4 kk = *(const float4*)(k + (pos * HKV + h) * DIM + d4);
            const float4 vv = *(const float4*)(v + (pos * HKV + h) * DIM + d4);
            const float4 pk = *(const float4*)(pek + l * DIM + d4);
            const float4 pv = *(const float4*)(pev + l * DIM + d4);
            float4 ok; ok.x = kk.x + pk.x; ok.y = kk.y + pk.y; ok.z = kk.z + pk.z; ok.w = kk.w + pk.w;
            float4 ov; ov.x = vv.x + pv.x; ov.y = vv.y + pv.y; ov.z = vv.z + pv.z; ov.w = vv.w + pv.w;
            *(float4*)(xk + tt * 4096 + l * DIM + d4) = ok;
            *(float4*)(xv + tt * 4096 + l * DIM + d4) = ov;
        }
    }
    __syncthreads();

    float ak[2] = {0.f, 0.f};
    float av[2] = {0.f, 0.f};
    const int i0 = seg * 256;
#pragma unroll 4
    for (int i = i0; i < i0 + 256; ++i) {
        float wk = Wk[i * DIM + e];
        float wv = Wv[i * DIM + e];
#pragma unroll
        for (int tt = 0; tt < 2; ++tt) {
            ak[tt] += xk[tt * 4096 + i] * wk;
            av[tt] += xv[tt * 4096 + i] * wv;
        }
    }
#pragma unroll
    for (int tt = 0; tt < 2; ++tt) {
        red[((0 * 16 + seg) * 2 + tt) * 32 + lane] = ak[tt];
        red[((1 * 16 + seg) * 2 + tt) * 32 + lane] = av[tt];
    }
    __syncthreads();

    if (tid < 128) {
        int b  = tid >> 6;
        int tt = (tid >> 5) & 1;
        int ee = tid & 31;
        int t  = t0 + tt;
        if (t < Tc) {
            float sv = 0.f;
#pragma unroll
            for (int sg = 0; sg < 16; ++sg)
                sv += red[((b * 16 + sg) * 2 + tt) * 32 + ee];
            if (b == 0) g_ck[(t * HKV + h) * DIM + e0 + ee] = sv + bk[e0 + ee];
            else        g_cv[(t * HKV + h) * DIM + e0 + ee] = sv + bv[e0 + ee];
        }
    }
}

// =====================================================================
// Kernel B: compressed attention + pooled top-k selection
// grid (S, HKV), block 256 (8 warps = 8 heads of the GQA group)
// =====================================================================
__global__ __launch_bounds__(256, 4)
void cmpattn_kernel(const float* __restrict__ q, int S, int Tc)
{
    __shared__ float qs[8][DIM];
    __shared__ float cl[8][96];
    __shared__ float sc[96];
    __shared__ float pooled[NKBLK];

    const int s    = blockIdx.x;
    const int hkv  = blockIdx.y;
    const int tid  = threadIdx.x;
    const int g    = tid >> 5;
    const int lane = tid & 31;

    for (int i = tid; i < 8 * DIM; i += 256) {
        int gg = i >> 7, d = i & 127;
        qs[gg][d] = q[(s * HQ + hkv * 8 + gg) * DIM + d];
    }
    __syncthreads();

    int tvis = (s >= 31) ? ((s - 31) / 16 + 1) : 0;
    if (tvis > Tc) tvis = Tc;

    float q0 = qs[g][lane], q1 = qs[g][lane + 32];
    float q2 = qs[g][lane + 64], q3 = qs[g][lane + 96];

    for (int t = 0; t < tvis; ++t) {
        const float* ckp = &g_ck[(t * HKV + hkv) * DIM];
        float p = q0 * ckp[lane] + q1 * ckp[lane + 32] +
                  q2 * ckp[lane + 64] + q3 * ckp[lane + 96];
#pragma unroll
        for (int o = 16; o; o >>= 1) p += __shfl_xor_sync(0xffffffffu, p, o);
        if (lane == 0) cl[g][t] = p * SCALE;
    }
    __syncwarp();

    // softmax over t < tvis (no max-subtraction needed: |logit| < ~10)
    float ssum = 0.f;
    for (int t = lane; t < tvis; t += 32) { float e_ = __expf(cl[g][t]); cl[g][t] = e_; ssum += e_; }
#pragma unroll
    for (int o = 16; o; o >>= 1) ssum += __shfl_xor_sync(0xffffffffu, ssum, o);
    float inv = 1.0f / fmaxf(ssum, 1e-9f);
    for (int t = lane; t < tvis; t += 32) cl[g][t] *= inv;
    for (int t = tvis + lane; t < 96; t += 32) cl[g][t] = 0.f;
    __syncwarp();

    // compressed-branch output
    float a0 = 0.f, a1 = 0.f, a2 = 0.f, a3 = 0.f;
    for (int t = 0; t < tvis; ++t) {
        float p = cl[g][t];
        const float* cvp = &g_cv[(t * HKV + hkv) * DIM];
        a0 += p * cvp[lane];      a1 += p * cvp[lane + 32];
        a2 += p * cvp[lane + 64]; a3 += p * cvp[lane + 96];
    }
    float* outp = &g_cmp[(s * HQ + hkv * 8 + g) * DIM];
    outp[lane] = a0; outp[lane + 32] = a1; outp[lane + 64] = a2; outp[lane + 96] = a3;
    __syncthreads();

    // GQA-summed score
    for (int t = tid; t < Tc; t += 256) {
        float sv = 0.f;
#pragma unroll
        for (int gg = 0; gg < 8; ++gg) sv += cl[gg][t];
        sc[t] = sv;
    }
    __syncthreads();

    // avg-pool (kernel 5, stride 4, ceil_mode, count-include-pad w/ P=0)
    if (tid < NKBLK) {
        float sum = 0.f; int cnt = 0;
#pragma unroll
        for (int j = 0; j < 5; ++j) {
            int idx = tid * 4 + j;
            if (idx < Tc) { sum += sc[idx]; cnt++; }
        }
        pooled[tid] = sum / (float)cnt;
    }
    __syncthreads();

    // top-16 of 24 with jax tie rule (lower index wins)
    if (tid < 32) {
        unsigned selbit = 0;
        if (tid < NKBLK) {
            float vme = pooled[tid];
            int rank = 0;
#pragma unroll
            for (int o = 0; o < NKBLK; ++o) {
                float vo = pooled[o];
                if (vo > vme || (vo == vme && o < tid)) rank++;
            }
            selbit = (rank < 16) ? 1u : 0u;
        }
        unsigned msk = __ballot_sync(0xffffffffu, selbit);
        if (tid == 0) g_sel[hkv * S + s] = msk;
    }
}

// Fast-path AV: one stream, one accumulator target, no predication.
#define AV_FAST(ACC)                                                        \
    for (int u = 0; u < 32; ++u) {                                          \
        float v0 = vs[u * KPAD + lane];                                     \
        float v1 = vs[u * KPAD + lane + 32];                                \
        float v2 = vs[u * KPAD + lane + 64];                                \
        float v3 = vs[u * KPAD + lane + 96];                                \
        _Pragma("unroll")                                                   \
        for (int j = 0; j < 4; ++j) {                                       \
            float p = ps[(w * 8 + j) * 32 + u];                             \
            ACC[j][0] += p * v0; ACC[j][1] += p * v1;                       \
            ACC[j][2] += p * v2; ACC[j][3] += p * v3;                       \
        }                                                                   \
    }

// =====================================================================
// Kernel C: block-sparse + sliding-window attention, gated combine.
// QT=32, block 256 (8 warps x 4 queries), 3 CTAs/SM target.
// Warp-uniform per-tile mode dispatch (BOTH/SEL/WIN/fallback).
// grid (S/32, HQ)
// =====================================================================
__global__ __launch_bounds__(256, 3)
void mainattn_kernel(const float* __restrict__ q, const float* __restrict__ k,
                     const float* __restrict__ v, const float* __restrict__ Wg,
                     const float* __restrict__ bg, float* __restrict__ out, int S)
{
    extern __shared__ float sm[];
    float*    qs   = sm;                       // QT*128
    float*    ks   = qs + QT * DIM;            // 32*KPAD
    float*    vs   = ks + 32 * KPAD;           // 32*KPAD
    float*    ps   = vs + 32 * KPAD;           // 8*8*32
    unsigned* selm = (unsigned*)(ps + 8 * 8 * 32);    // QT + 1(union)

    const int qtile = (gridDim.x - 1) - blockIdx.x;   // heavy tiles first
    const int h     = blockIdx.y;
    const int hkv   = h >> 3;
    const int qbase = qtile * QT;
    const int tid   = threadIdx.x;
    const int w     = tid >> 5;
    const int lane  = tid & 31;

    // vectorized Q fill: QT*128 floats = QT*32 float4
    for (int f = tid; f < QT * 32; f += 256) {
        int ql = f >> 5, d4 = (f & 31) << 2;
        *(float4*)(qs + ql * DIM + d4) =
            *(const float4*)(q + ((qbase + ql) * HQ + h) * DIM + d4);
    }
    if (tid < QT) selm[tid] = g_sel[hkv * S + qbase + tid];
    __syncthreads();
    if (tid == 0) {
        unsigned u = 0;
#pragma unroll 8
        for (int i = 0; i < QT; ++i) u |= selm[i];
        selm[QT] = u;
    }
    __syncthreads();
    const unsigned unionmask = selm[QT];

    int sj[4];
#pragma unroll
    for (int j = 0; j < 4; ++j) sj[j] = qbase + w * 4 + j;
    const int wlo0 = sj[0] - (WIN - 1);
    const int wlo3 = sj[3] - (WIN - 1);

    float sumS[4], sumW[4], accC[4][4], accSo[4][4], accWo[4][4];
#pragma unroll
    for (int j = 0; j < 4; ++j) {
        sumS[j] = 0.f; sumW[j] = 0.f;
#pragma unroll
        for (int kk = 0; kk < 4; ++kk) { accC[j][kk] = 0.f; accSo[j][kk] = 0.f; accWo[j][kk] = 0.f; }
    }

    const int nkt = (qbase + QT) >> 5;
    for (int kt = 0; kt < nkt; ++kt) {
        const int u0 = kt << 5;
        // CTA-uniform skip: no query in this CTA needs this key block
        bool ctaSel = (unionmask >> (u0 >> 6)) & 1u;
        bool ctaWin = (u0 + 31 >= qbase - (WIN - 1));
        if (!ctaSel && !ctaWin) continue;

        __syncthreads();
        // vectorized K/V fill: 32*128 floats = 1024 float4 each
        for (int f = tid; f < 1024; f += 256) {
            int u = f >> 5, d4 = (f & 31) << 2;
            int gk = ((u0 + u) * HKV + hkv) * DIM + d4;
            *(float4*)(ks + u * KPAD + d4) = *(const float4*)(k + gk);
            *(float4*)(vs + u * KPAD + d4) = *(const float4*)(v + gk);
        }
        __syncthreads();

        if (u0 > sj[3]) continue;  // all block syncs for this iter already done

        const int kb = u0 >> 6;
        bool sq[4];
#pragma unroll
        for (int j = 0; j < 4; ++j) sq[j] = (selm[w * 4 + j] >> kb) & 1u;
        const bool selAll  = sq[0] && sq[1] && sq[2] && sq[3];
        const bool selAny  = sq[0] || sq[1] || sq[2] || sq[3];
        const bool causalAll  = (u0 + 31 <= sj[0]);     // no causal masking needed
        const bool fullWinAll = (u0 >= wlo3);           // every key in window, all j
        const bool noWinAll   = (u0 + 31 < wlo0);       // no key in window, any j

        int mode;
        if (causalAll && selAll && fullWinAll)       mode = 0;   // BOTH
        else if (causalAll && selAll && noWinAll)    mode = 1;   // SEL
        else if (causalAll && !selAny && fullWinAll) mode = 2;   // WIN
        else if (causalAll && !selAny && noWinAll)   continue;   // nothing
        else                                         mode = 3;   // fallback

        bool needS[4], needW[4], needA[4];
        if (mode == 3) {
            bool any = false;
#pragma unroll
            for (int j = 0; j < 4; ++j) {
                bool act = (u0 <= sj[j]);
                needS[j] = act && sq[j];
                needW[j] = act && (u0 + 31 >= sj[j] - (WIN - 1));
                needA[j] = needS[j] || needW[j];
                any |= needA[j];
            }
            if (!any) continue;
        }

        // ---- QK (shared by all modes) ----
        const float4* k4 = (const float4*)(ks + lane * KPAD);
        float lg[4] = {0.f, 0.f, 0.f, 0.f};
#pragma unroll 8
        for (int c = 0; c < 32; ++c) {
            float4 kv4 = k4[c];
#pragma unroll
            for (int j = 0; j < 4; ++j) {
                float4 q4 = *(const float4*)(qs + (w * 4 + j) * DIM + 4 * c);
                lg[j] += q4.x * kv4.x + q4.y * kv4.y + q4.z * kv4.z + q4.w * kv4.w;
            }
        }

        if (mode == 0) {          // BOTH: one stream, counts in both branches
#pragma unroll
            for (int j = 0; j < 4; ++j) {
                float e = __expf(lg[j] * SCALE);
                ps[(w * 8 + j) * 32 + lane] = e;
                sumS[j] += e; sumW[j] += e;
            }
            __syncwarp();
            AV_FAST(accC)
            __syncwarp();
        } else if (mode == 1) {   // SEL only
#pragma unroll
            for (int j = 0; j < 4; ++j) {
                float e = __expf(lg[j] * SCALE);
                ps[(w * 8 + j) * 32 + lane] = e;
                sumS[j] += e;
            }
            __syncwarp();
            AV_FAST(accSo)
            __syncwarp();
        } else if (mode == 2) {   // WIN only
#pragma unroll
            for (int j = 0; j < 4; ++j) {
                float e = __expf(lg[j] * SCALE);
                ps[(w * 8 + j) * 32 + lane] = e;
                sumW[j] += e;
            }
            __syncwarp();
            AV_FAST(accWo)
            __syncwarp();
        } else {                  // fallback: generic two-stream
            const int ku = u0 + lane;
#pragma unroll
            for (int j = 0; j < 4; ++j) {
                if (!needA[j]) continue;
                bool causal = (ku <= sj[j]);
                bool mS = causal && needS[j];
                bool mW = causal && needW[j] && (ku >= sj[j] - (WIN - 1));
                float e = (mS || mW) ? __expf(lg[j] * SCALE) : 0.f;
                if (needS[j]) {
                    float pS = mS ? e : 0.f;
                    sumS[j] += pS;
                    ps[(w * 8 + j * 2 + 0) * 32 + lane] = pS;
                }
                if (needW[j]) {
                    float pW = mW ? e : 0.f;
                    sumW[j] += pW;
                    ps[(w * 8 + j * 2 + 1) * 32 + lane] = pW;
                }
            }
            __syncwarp();
            for (int u = 0; u < 32; ++u) {
                float v0 = vs[u * KPAD + lane];
                float v1 = vs[u * KPAD + lane + 32];
                float v2 = vs[u * KPAD + lane + 64];
                float v3 = vs[u * KPAD + lane + 96];
#pragma unroll
                for (int j = 0; j < 4; ++j) {
                    if (needS[j]) {
                        float pS = ps[(w * 8 + j * 2 + 0) * 32 + u];
                        accSo[j][0] += pS * v0; accSo[j][1] += pS * v1;
                        accSo[j][2] += pS * v2; accSo[j][3] += pS * v3;
                    }
                    if (needW[j]) {
                        float pW = ps[(w * 8 + j * 2 + 1) * 32 + u];
                        accWo[j][0] += pW * v0; accWo[j][1] += pW * v1;
                        accWo[j][2] += pW * v2; accWo[j][3] += pW * v3;
                    }
                }
            }
            __syncwarp();
        }
    }

    // epilogue: reduce denominators once, gate + combine
#pragma unroll
    for (int j = 0; j < 4; ++j) {
        const int s = sj[j];
        float rs = sumS[j], rw = sumW[j];
#pragma unroll
        for (int o = 16; o; o >>= 1) {
            rs += __shfl_xor_sync(0xffffffffu, rs, o);
            rw += __shfl_xor_sync(0xffffffffu, rw, o);
        }
        float invS = 1.0f / fmaxf(rs, 1e-9f);
        float invW = 1.0f / fmaxf(rw, 1e-9f);

        const float* qrow = qs + (w * 4 + j) * DIM;
        float g0 = 0.f, g1 = 0.f, g2 = 0.f;
#pragma unroll
        for (int kk = 0; kk < 4; ++kk) {
            int d = lane + 32 * kk;
            float qv = qrow[d];
            g0 += qv * Wg[d * 3 + 0];
            g1 += qv * Wg[d * 3 + 1];
            g2 += qv * Wg[d * 3 + 2];
        }
#pragma unroll
        for (int o = 16; o; o >>= 1) {
            g0 += __shfl_xor_sync(0xffffffffu, g0, o);
            g1 += __shfl_xor_sync(0xffffffffu, g1, o);
            g2 += __shfl_xor_sync(0xffffffffu, g2, o);
        }
        g0 = 1.0f / (1.0f + __expf(-(g0 + bg[0])));
        g1 = 1.0f / (1.0f + __expf(-(g1 + bg[1])));
        g2 = 1.0f / (1.0f + __expf(-(g2 + bg[2])));

        const float* cm = &g_cmp[(s * HQ + h) * DIM];
        float* op = out + (s * HQ + h) * DIM;
#pragma unroll
        for (int kk = 0; kk < 4; ++kk) {
            int d = lane + 32 * kk;
            float aS = accC[j][kk] + accSo[j][kk];
            float aW = accC[j][kk] + accWo[j][kk];
            op[d] = g0 * (aS * invS) + g1 * (aW * invW) + g2 * cm[d];
        }
    }
}

// =====================================================================
extern "C" void kernel_launch(void* const* d_in, const int* in_sizes, int n_in,
                              void* d_out, int out_size)
{
    const float* q   = (const float*)d_in[0];
    const float* k   = (const float*)d_in[1];
    const float* v   = (const float*)d_in[2];
    const float* Wk  = (const float*)d_in[3];
    const float* bk  = (const float*)d_in[4];
    const float* Wv  = (const float*)d_in[5];
    const float* bv  = (const float*)d_in[6];
    const float* pek = (const float*)d_in[7];
    const float* pev = (const float*)d_in[8];
    const float* Wg  = (const float*)d_in[9];
    const float* bg  = (const float*)d_in[10];
    float* out = (float*)d_out;

    const int S  = in_sizes[0] / (HQ * DIM);
    const int Tc = (S - 32) / 16 + 1;

    const int smemA = (4 * 4096 + 2 * 16 * 2 * 32) * (int)sizeof(float);   // 73728
    const int smemC = (QT * DIM + 2 * 32 * KPAD + 8 * 8 * 32) * (int)sizeof(float)
                      + (QT + 8) * (int)sizeof(unsigned);                  // ~58.6 KB

    cudaFuncSetAttribute(compress_kernel, cudaFuncAttributeMaxDynamicSharedMemorySize, smemA);
    cudaFuncSetAttribute(mainattn_kernel, cudaFuncAttributeMaxDynamicSharedMemorySize, smemC);

    dim3 gA((Tc + 1) / 2, HKV, 4);
    compress_kernel<<<gA, 512, smemA>>>(k, v, Wk, bk, Wv, bv, pek, pev, S, Tc);

    dim3 gB(S, HKV);
    cmpattn_kernel<<<gB, 256>>>(q, S, Tc);

    dim3 gC(S / QT, HQ);
    mainattn_kernel<<<gC, 256, smemC>>>(q, k, v, Wg, bg, out, S);
}

// round 9
// speedup vs baseline: 1.5081x; 1.5081x over previous
#include <cuda_runtime.h>
#include <math.h>
#include <stdint.h>

// Problem constants (fixed for this dataset instance)
#define HQ   16
#define HKV  2
#define DIM  128
#define SCALE 0.08838834764831845f   // 1/sqrt(128)
#define MAXS   1536
#define MAXTC  95
#define NKBLK  24                    // S/64
#define WIN    512
#define KPAD 132                     // K/V row pad: 16B-aligned, conflict-free float4
#define TILEF (32 * KPAD)            // floats per K or V tile buffer

// ---------------- device scratch (static, no allocation) ----------------
__device__ float    g_ck [MAXTC * HKV * DIM];
__device__ float    g_cv [MAXTC * HKV * DIM];
__device__ float    g_cmp[MAXS * HQ * DIM];      // compressed-branch output
__device__ unsigned g_sel[HKV * MAXS];           // 24-bit selected-block mask

__device__ __forceinline__ void cp16(void* smem, const void* g) {
    uint32_t a = (uint32_t)__cvta_generic_to_shared(smem);
    asm volatile("cp.async.cg.shared.global [%0], [%1], 16;" :: "r"(a), "l"(g));
}

// =====================================================================
// Kernel A: compressed K/V   ck[t,h,:] = (blk(k)+pek) @ Wk + bk
// grid (ceil(Tc/2), HKV, 4[e-split]), block 512, 2 CTAs/SM
// =====================================================================
__global__ __launch_bounds__(512, 2)
void compress_kernel(const float* __restrict__ k, const float* __restrict__ v,
                     const float* __restrict__ Wk, const float* __restrict__ bk,
                     const float* __restrict__ Wv, const float* __restrict__ bv,
                     const float* __restrict__ pek, const float* __restrict__ pev,
                     int S, int Tc)
{
    extern __shared__ float sm[];
    float* xk  = sm;               // [2][4096]
    float* xv  = sm + 2 * 4096;    // [2][4096]
    float* red = sm + 4 * 4096;    // [2][16seg][2tt][32]

    const int h   = blockIdx.y;
    const int t0  = blockIdx.x * 2;
    const int e0  = blockIdx.z * 32;
    const int tid = threadIdx.x;
    const int seg = tid >> 5;          // 0..15
    const int lane = tid & 31;
    const int e   = e0 + lane;

    for (int tt = 0; tt < 2; ++tt) {
        int t = t0 + tt;
        if (t >= Tc) break;
        for (int f = tid; f < 1024; f += 512) {
            int l = f >> 5, d4 = (f & 31) << 2;
            int pos = t * 16 + l;
            const float4 kk = *(const float4*)(k + (pos * HKV + h) * DIM + d4);
            const float4 vv = *(const float4*)(v + (pos * HKV + h) * DIM + d4);
            const float4 pk = *(const float4*)(pek + l * DIM + d4);
            const float4 pv = *(const float4*)(pev + l * DIM + d4);
            float4 ok; ok.x = kk.x + pk.x; ok.y = kk.y + pk.y; ok.z = kk.z + pk.z; ok.w = kk.w + pk.w;
            float4 ov; ov.x = vv.x + pv.x; ov.y = vv.y + pv.y; ov.z = vv.z + pv.z; ov.w = vv.w + pv.w;
            *(float4*)(xk + tt * 4096 + l * DIM + d4) = ok;
            *(float4*)(xv + tt * 4096 + l * DIM + d4) = ov;
        }
    }
    __syncthreads();

    float ak[2] = {0.f, 0.f};
    float av[2] = {0.f, 0.f};
    const int i0 = seg * 256;
#pragma unroll 4
    for (int i = i0; i < i0 + 256; ++i) {
        float wk = Wk[i * DIM + e];
        float wv = Wv[i * DIM + e];
#pragma unroll
        for (int tt = 0; tt < 2; ++tt) {
            ak[tt] += xk[tt * 4096 + i] * wk;
            av[tt] += xv[tt * 4096 + i] * wv;
        }
    }
#pragma unroll
    for (int tt = 0; tt < 2; ++tt) {
        red[((0 * 16 + seg) * 2 + tt) * 32 + lane] = ak[tt];
        red[((1 * 16 + seg) * 2 + tt) * 32 + lane] = av[tt];
    }
    __syncthreads();

    if (tid < 128) {
        int b  = tid >> 6;
        int tt = (tid >> 5) & 1;
        int ee = tid & 31;
        int t  = t0 + tt;
        if (t < Tc) {
            float sv = 0.f;
#pragma unroll
            for (int sg = 0; sg < 16; ++sg)
                sv += red[((b * 16 + sg) * 2 + tt) * 32 + ee];
            if (b == 0) g_ck[(t * HKV + h) * DIM + e0 + ee] = sv + bk[e0 + ee];
            else        g_cv[(t * HKV + h) * DIM + e0 + ee] = sv + bv[e0 + ee];
        }
    }
}

// =====================================================================
// Kernel B: compressed attention + pooled top-k selection
// grid (S, HKV), block 256 (8 warps = 8 heads of the GQA group)
// =====================================================================
__global__ __launch_bounds__(256, 4)
void cmpattn_kernel(const float* __restrict__ q, int S, int Tc)
{
    __shared__ float qs[8][DIM];
    __shared__ float cl[8][96];
    __shared__ float sc[96];
    __shared__ float pooled[NKBLK];

    const int s    = blockIdx.x;
    const int hkv  = blockIdx.y;
    const int tid  = threadIdx.x;
    const int g    = tid >> 5;
    const int lane = tid & 31;

    for (int i = tid; i < 8 * DIM; i += 256) {
        int gg = i >> 7, d = i & 127;
        qs[gg][d] = q[(s * HQ + hkv * 8 + gg) * DIM + d];
    }
    __syncthreads();

    int tvis = (s >= 31) ? ((s - 31) / 16 + 1) : 0;
    if (tvis > Tc) tvis = Tc;

    float q0 = qs[g][lane], q1 = qs[g][lane + 32];
    float q2 = qs[g][lane + 64], q3 = qs[g][lane + 96];

    for (int t = 0; t < tvis; ++t) {
        const float* ckp = &g_ck[(t * HKV + hkv) * DIM];
        float p = q0 * ckp[lane] + q1 * ckp[lane + 32] +
                  q2 * ckp[lane + 64] + q3 * ckp[lane + 96];
#pragma unroll
        for (int o = 16; o; o >>= 1) p += __shfl_xor_sync(0xffffffffu, p, o);
        if (lane == 0) cl[g][t] = p * SCALE;
    }
    __syncwarp();

    // softmax over t < tvis (no max-subtraction needed: |logit| < ~10)
    float ssum = 0.f;
    for (int t = lane; t < tvis; t += 32) { float e_ = __expf(cl[g][t]); cl[g][t] = e_; ssum += e_; }
#pragma unroll
    for (int o = 16; o; o >>= 1) ssum += __shfl_xor_sync(0xffffffffu, ssum, o);
    float inv = 1.0f / fmaxf(ssum, 1e-9f);
    for (int t = lane; t < tvis; t += 32) cl[g][t] *= inv;
    for (int t = tvis + lane; t < 96; t += 32) cl[g][t] = 0.f;
    __syncwarp();

    // compressed-branch output
    float a0 = 0.f, a1 = 0.f, a2 = 0.f, a3 = 0.f;
    for (int t = 0; t < tvis; ++t) {
        float p = cl[g][t];
        const float* cvp = &g_cv[(t * HKV + hkv) * DIM];
        a0 += p * cvp[lane];      a1 += p * cvp[lane + 32];
        a2 += p * cvp[lane + 64]; a3 += p * cvp[lane + 96];
    }
    float* outp = &g_cmp[(s * HQ + hkv * 8 + g) * DIM];
    outp[lane] = a0; outp[lane + 32] = a1; outp[lane + 64] = a2; outp[lane + 96] = a3;
    __syncthreads();

    // GQA-summed score
    for (int t = tid; t < Tc; t += 256) {
        float sv = 0.f;
#pragma unroll
        for (int gg = 0; gg < 8; ++gg) sv += cl[gg][t];
        sc[t] = sv;
    }
    __syncthreads();

    // avg-pool (kernel 5, stride 4, ceil_mode, count-include-pad w/ P=0)
    if (tid < NKBLK) {
        float sum = 0.f; int cnt = 0;
#pragma unroll
        for (int j = 0; j < 5; ++j) {
            int idx = tid * 4 + j;
            if (idx < Tc) { sum += sc[idx]; cnt++; }
        }
        pooled[tid] = sum / (float)cnt;
    }
    __syncthreads();

    // top-16 of 24 with jax tie rule (lower index wins)
    if (tid < 32) {
        unsigned selbit = 0;
        if (tid < NKBLK) {
            float vme = pooled[tid];
            int rank = 0;
#pragma unroll
            for (int o = 0; o < NKBLK; ++o) {
                float vo = pooled[o];
                if (vo > vme || (vo == vme && o < tid)) rank++;
            }
            selbit = (rank < 16) ? 1u : 0u;
        }
        unsigned msk = __ballot_sync(0xffffffffu, selbit);
        if (tid == 0) g_sel[hkv * S + s] = msk;
    }
}

// Fast-path AV: one stream, one accumulator target, no predication.
#define AV_FAST(ACC)                                                        \
    for (int u = 0; u < 32; ++u) {                                          \
        float v0 = vs[u * KPAD + lane];                                     \
        float v1 = vs[u * KPAD + lane + 32];                                \
        float v2 = vs[u * KPAD + lane + 64];                                \
        float v3 = vs[u * KPAD + lane + 96];                                \
        _Pragma("unroll")                                                   \
        for (int j = 0; j < 4; ++j) {                                       \
            float p = ps[(w * 8 + j) * 32 + u];                             \
            ACC[j][0] += p * v0; ACC[j][1] += p * v1;                       \
            ACC[j][2] += p * v2; ACC[j][3] += p * v3;                       \
        }                                                                   \
    }

// =====================================================================
// Kernel C: block-sparse + sliding-window attention, gated combine.
// R7 shape (QT=64, block 512, 1 CTA/SM, warp-uniform mode dispatch)
// + cp.async double-buffered K/V tiles: tile i+1's fill overlaps tile i's
// compute, removing the per-tile fill latency from the critical path.
// grid (S/64, HQ)
// =====================================================================
__global__ __launch_bounds__(512, 1)
void mainattn_kernel(const float* __restrict__ q, const float* __restrict__ k,
                     const float* __restrict__ v, const float* __restrict__ Wg,
                     const float* __restrict__ bg, float* __restrict__ out, int S)
{
    extern __shared__ float sm[];
    float*    qs   = sm;                       // 64*128
    float*    ksb  = qs + 64 * DIM;            // 2 x 32*KPAD
    float*    vsb  = ksb + 2 * TILEF;          // 2 x 32*KPAD
    float*    ps   = vsb + 2 * TILEF;          // 16*8*32
    unsigned* selm = (unsigned*)(ps + 16 * 8 * 32);   // 64 + 1(union)

    const int qtile = (gridDim.x - 1) - blockIdx.x;   // heavy tiles first
    const int h     = blockIdx.y;
    const int hkv   = h >> 3;
    const int qbase = qtile * 64;
    const int tid   = threadIdx.x;
    const int w     = tid >> 5;
    const int lane  = tid & 31;

    // vectorized Q fill: 64*128 floats = 2048 float4
    for (int f = tid; f < 2048; f += 512) {
        int ql = f >> 5, d4 = (f & 31) << 2;
        *(float4*)(qs + ql * DIM + d4) =
            *(const float4*)(q + ((qbase + ql) * HQ + h) * DIM + d4);
    }
    if (tid < 64) selm[tid] = g_sel[hkv * S + qbase + tid];
    __syncthreads();
    if (tid == 0) {
        unsigned u = 0;
#pragma unroll 8
        for (int i = 0; i < 64; ++i) u |= selm[i];
        selm[64] = u;
    }
    __syncthreads();
    const unsigned unionmask = selm[64];

    int sj[4];
#pragma unroll
    for (int j = 0; j < 4; ++j) sj[j] = qbase + w * 4 + j;
    const int wlo0 = sj[0] - (WIN - 1);
    const int wlo3 = sj[3] - (WIN - 1);
    const int winloCTA = qbase - (WIN - 1);

    float sumS[4], sumW[4], accC[4][4], accSo[4][4], accWo[4][4];
#pragma unroll
    for (int j = 0; j < 4; ++j) {
        sumS[j] = 0.f; sumW[j] = 0.f;
#pragma unroll
        for (int kk = 0; kk < 4; ++kk) { accC[j][kk] = 0.f; accSo[j][kk] = 0.f; accWo[j][kk] = 0.f; }
    }

    const int nkt = (qbase + 64) >> 5;

    // prefetch cursor over *needed* tiles only
    int cur = -1;
    for (int t = 0; t < nkt; ++t) {
        int u0t = t << 5;
        if (((unionmask >> (u0t >> 6)) & 1u) || (u0t + 31 >= winloCTA)) { cur = t; break; }
    }
    int buf = 0;
    if (cur >= 0) {
        const int u0 = cur << 5;
        float* kd = ksb; float* vd = vsb;
        for (int f = tid; f < 1024; f += 512) {
            int u = f >> 5, d4 = (f & 31) << 2;
            int gk = ((u0 + u) * HKV + hkv) * DIM + d4;
            cp16(kd + u * KPAD + d4, k + gk);
            cp16(vd + u * KPAD + d4, v + gk);
        }
        asm volatile("cp.async.commit_group;" ::: "memory");
    }

    while (cur >= 0) {
        int nxt = -1;
        for (int t = cur + 1; t < nkt; ++t) {
            int u0t = t << 5;
            if (((unionmask >> (u0t >> 6)) & 1u) || (u0t + 31 >= winloCTA)) { nxt = t; break; }
        }
        asm volatile("cp.async.wait_group 0;" ::: "memory");
        __syncthreads();                       // current tile visible to all

        if (nxt >= 0) {                        // overlap next fill with compute
            const int u0n = nxt << 5;
            float* kd = ksb + (buf ^ 1) * TILEF;
            float* vd = vsb + (buf ^ 1) * TILEF;
            for (int f = tid; f < 1024; f += 512) {
                int u = f >> 5, d4 = (f & 31) << 2;
                int gk = ((u0n + u) * HKV + hkv) * DIM + d4;
                cp16(kd + u * KPAD + d4, k + gk);
                cp16(vd + u * KPAD + d4, v + gk);
            }
            asm volatile("cp.async.commit_group;" ::: "memory");
        }

        const float* ks = ksb + buf * TILEF;
        const float* vs = vsb + buf * TILEF;
        const int u0 = cur << 5;

        if (u0 <= sj[3]) {
            const int kb = u0 >> 6;
            bool sq[4];
#pragma unroll
            for (int j = 0; j < 4; ++j) sq[j] = (selm[w * 4 + j] >> kb) & 1u;
            const bool selAll  = sq[0] && sq[1] && sq[2] && sq[3];
            const bool selAny  = sq[0] || sq[1] || sq[2] || sq[3];
            const bool causalAll  = (u0 + 31 <= sj[0]);
            const bool fullWinAll = (u0 >= wlo3);
            const bool noWinAll   = (u0 + 31 < wlo0);

            int mode;
            if (causalAll && selAll && fullWinAll)       mode = 0;   // BOTH
            else if (causalAll && selAll && noWinAll)    mode = 1;   // SEL
            else if (causalAll && !selAny && fullWinAll) mode = 2;   // WIN
            else if (causalAll && !selAny && noWinAll)   mode = -1;  // nothing
            else                                         mode = 3;   // fallback

            bool needS[4], needW[4], needA[4];
            if (mode == 3) {
                bool any = false;
#pragma unroll
                for (int j = 0; j < 4; ++j) {
                    bool act = (u0 <= sj[j]);
                    needS[j] = act && sq[j];
                    needW[j] = act && (u0 + 31 >= sj[j] - (WIN - 1));
                    needA[j] = needS[j] || needW[j];
                    any |= needA[j];
                }
                if (!any) mode = -1;
            }

            if (mode >= 0) {
                // ---- QK (shared by all modes) ----
                const float4* k4 = (const float4*)(ks + lane * KPAD);
                float lg[4] = {0.f, 0.f, 0.f, 0.f};
#pragma unroll 8
                for (int c = 0; c < 32; ++c) {
                    float4 kv4 = k4[c];
#pragma unroll
                    for (int j = 0; j < 4; ++j) {
                        float4 q4 = *(const float4*)(qs + (w * 4 + j) * DIM + 4 * c);
                        lg[j] += q4.x * kv4.x + q4.y * kv4.y + q4.z * kv4.z + q4.w * kv4.w;
                    }
                }

                if (mode == 0) {          // BOTH
#pragma unroll
                    for (int j = 0; j < 4; ++j) {
                        float e = __expf(lg[j] * SCALE);
                        ps[(w * 8 + j) * 32 + lane] = e;
                        sumS[j] += e; sumW[j] += e;
                    }
                    __syncwarp();
                    AV_FAST(accC)
                    __syncwarp();
                } else if (mode == 1) {   // SEL only
#pragma unroll
                    for (int j = 0; j < 4; ++j) {
                        float e = __expf(lg[j] * SCALE);
                        ps[(w * 8 + j) * 32 + lane] = e;
                        sumS[j] += e;
                    }
                    __syncwarp();
                    AV_FAST(accSo)
                    __syncwarp();
                } else if (mode == 2) {   // WIN only
#pragma unroll
                    for (int j = 0; j < 4; ++j) {
                        float e = __expf(lg[j] * SCALE);
                        ps[(w * 8 + j) * 32 + lane] = e;
                        sumW[j] += e;
                    }
                    __syncwarp();
                    AV_FAST(accWo)
                    __syncwarp();
                } else {                  // fallback: generic two-stream
                    const int ku = u0 + lane;
#pragma unroll
                    for (int j = 0; j < 4; ++j) {
                        if (!needA[j]) continue;
                        bool causal = (ku <= sj[j]);
                        bool mS = causal && needS[j];
                        bool mW = causal && needW[j] && (ku >= sj[j] - (WIN - 1));
                        float e = (mS || mW) ? __expf(lg[j] * SCALE) : 0.f;
                        if (needS[j]) {
                            float pS = mS ? e : 0.f;
                            sumS[j] += pS;
                            ps[(w * 8 + j * 2 + 0) * 32 + lane] = pS;
                        }
                        if (needW[j]) {
                            float pW = mW ? e : 0.f;
                            sumW[j] += pW;
                            ps[(w * 8 + j * 2 + 1) * 32 + lane] = pW;
                        }
                    }
                    __syncwarp();
                    for (int u = 0; u < 32; ++u) {
                        float v0 = vs[u * KPAD + lane];
                        float v1 = vs[u * KPAD + lane + 32];
                        float v2 = vs[u * KPAD + lane + 64];
                        float v3 = vs[u * KPAD + lane + 96];
#pragma unroll
                        for (int j = 0; j < 4; ++j) {
                            if (needS[j]) {
                                float pS = ps[(w * 8 + j * 2 + 0) * 32 + u];
                                accSo[j][0] += pS * v0; accSo[j][1] += pS * v1;
                                accSo[j][2] += pS * v2; accSo[j][3] += pS * v3;
                            }
                            if (needW[j]) {
                                float pW = ps[(w * 8 + j * 2 + 1) * 32 + u];
                                accWo[j][0] += pW * v0; accWo[j][1] += pW * v1;
                                accWo[j][2] += pW * v2; accWo[j][3] += pW * v3;
                            }
                        }
                    }
                    __syncwarp();
                }
            }
        }

        __syncthreads();          // protect WAR: next iteration fills this buf
        cur = nxt; buf ^= 1;
    }

    // epilogue: reduce denominators once, gate + combine
#pragma unroll
    for (int j = 0; j < 4; ++j) {
        const int s = sj[j];
        float rs = sumS[j], rw = sumW[j];
#pragma unroll
        for (int o = 16; o; o >>= 1) {
            rs += __shfl_xor_sync(0xffffffffu, rs, o);
            rw += __shfl_xor_sync(0xffffffffu, rw, o);
        }
        float invS = 1.0f / fmaxf(rs, 1e-9f);
        float invW = 1.0f / fmaxf(rw, 1e-9f);

        const float* qrow = qs + (w * 4 + j) * DIM;
        float g0 = 0.f, g1 = 0.f, g2 = 0.f;
#pragma unroll
        for (int kk = 0; kk < 4; ++kk) {
            int d = lane + 32 * kk;
            float qv = qrow[d];
            g0 += qv * Wg[d * 3 + 0];
            g1 += qv * Wg[d * 3 + 1];
            g2 += qv * Wg[d * 3 + 2];
        }
#pragma unroll
        for (int o = 16; o; o >>= 1) {
            g0 += __shfl_xor_sync(0xffffffffu, g0, o);
            g1 += __shfl_xor_sync(0xffffffffu, g1, o);
            g2 += __shfl_xor_sync(0xffffffffu, g2, o);
        }
        g0 = 1.0f / (1.0f + __expf(-(g0 + bg[0])));
        g1 = 1.0f / (1.0f + __expf(-(g1 + bg[1])));
        g2 = 1.0f / (1.0f + __expf(-(g2 + bg[2])));

        const float* cm = &g_cmp[(s * HQ + h) * DIM];
        float* op = out + (s * HQ + h) * DIM;
#pragma unroll
        for (int kk = 0; kk < 4; ++kk) {
            int d = lane + 32 * kk;
            float aS = accC[j][kk] + accSo[j][kk];
            float aW = accC[j][kk] + accWo[j][kk];
            op[d] = g0 * (aS * invS) + g1 * (aW * invW) + g2 * cm[d];
        }
    }
}

// =====================================================================
extern "C" void kernel_launch(void* const* d_in, const int* in_sizes, int n_in,
                              void* d_out, int out_size)
{
    const float* q   = (const float*)d_in[0];
    const float* k   = (const float*)d_in[1];
    const float* v   = (const float*)d_in[2];
    const float* Wk  = (const float*)d_in[3];
    const float* bk  = (const float*)d_in[4];
    const float* Wv  = (const float*)d_in[5];
    const float* bv  = (const float*)d_in[6];
    const float* pek = (const float*)d_in[7];
    const float* pev = (const float*)d_in[8];
    const float* Wg  = (const float*)d_in[9];
    const float* bg  = (const float*)d_in[10];
    float* out = (float*)d_out;

    const int S  = in_sizes[0] / (HQ * DIM);
    const int Tc = (S - 32) / 16 + 1;

    const int smemA = (4 * 4096 + 2 * 16 * 2 * 32) * (int)sizeof(float);   // 73728
    const int smemC = (64 * DIM + 4 * TILEF + 16 * 8 * 32) * (int)sizeof(float)
                      + 72 * (int)sizeof(unsigned);                        // ~117 KB

    cudaFuncSetAttribute(compress_kernel, cudaFuncAttributeMaxDynamicSharedMemorySize, smemA);
    cudaFuncSetAttribute(mainattn_kernel, cudaFuncAttributeMaxDynamicSharedMemorySize, smemC);

    dim3 gA((Tc + 1) / 2, HKV, 4);
    compress_kernel<<<gA, 512, smemA>>>(k, v, Wk, bk, Wv, bv, pek, pev, S, Tc);

    dim3 gB(S, HKV);
    cmpattn_kernel<<<gB, 256>>>(q, S, Tc);

    dim3 gC(S / 64, HQ);
    mainattn_kernel<<<gC, 512, smemC>>>(q, k, v, Wg, bg, out, S);
}

// round 10
// speedup vs baseline: 2.2393x; 1.4848x over previous
#include <cuda_runtime.h>
#include <math.h>
#include <stdint.h>

// Problem constants (fixed for this dataset instance)
#define HQ   16
#define HKV  2
#define DIM  128
#define SCALE 0.08838834764831845f   // 1/sqrt(128)
#define MAXS   1536
#define MAXTC  95
#define NKBLK  24                    // S/64
#define WIN    512
#define KPAD 132                     // K/V row pad: 16B-aligned, conflict-free float4
#define TILEF (32 * KPAD)            // floats per K or V tile buffer

// ---------------- device scratch (static, no allocation) ----------------
__device__ float    g_ck [MAXTC * HKV * DIM];
__device__ float    g_cv [MAXTC * HKV * DIM];
__device__ float    g_cmp[MAXS * HQ * DIM];      // compressed-branch output
__device__ unsigned g_sel[HKV * MAXS];           // 24-bit selected-block mask

__device__ __forceinline__ void cp16(void* smem, const void* g) {
    uint32_t a = (uint32_t)__cvta_generic_to_shared(smem);
    asm volatile("cp.async.cg.shared.global [%0], [%1], 16;" :: "r"(a), "l"(g));
}

// =====================================================================
// Kernel A: compressed K/V   ck[t,h,:] = (blk(k)+pek) @ Wk + bk
// grid (ceil(Tc/2), HKV, 4[e-split]), block 512, 2 CTAs/SM
// =====================================================================
__global__ __launch_bounds__(512, 2)
void compress_kernel(const float* __restrict__ k, const float* __restrict__ v,
                     const float* __restrict__ Wk, const float* __restrict__ bk,
                     const float* __restrict__ Wv, const float* __restrict__ bv,
                     const float* __restrict__ pek, const float* __restrict__ pev,
                     int S, int Tc)
{
    extern __shared__ float sm[];
    float* xk  = sm;               // [2][4096]
    float* xv  = sm + 2 * 4096;    // [2][4096]
    float* red = sm + 4 * 4096;    // [2][16seg][2tt][32]

    const int h   = blockIdx.y;
    const int t0  = blockIdx.x * 2;
    const int e0  = blockIdx.z * 32;
    const int tid = threadIdx.x;
    const int seg = tid >> 5;          // 0..15
    const int lane = tid & 31;
    const int e   = e0 + lane;

    for (int tt = 0; tt < 2; ++tt) {
        int t = t0 + tt;
        if (t >= Tc) break;
        for (int f = tid; f < 1024; f += 512) {
            int l = f >> 5, d4 = (f & 31) << 2;
            int pos = t * 16 + l;
            const float4 kk = *(const float4*)(k + (pos * HKV + h) * DIM + d4);
            const float4 vv = *(const float4*)(v + (pos * HKV + h) * DIM + d4);
            const float4 pk = *(const float4*)(pek + l * DIM + d4);
            const float4 pv = *(const float4*)(pev + l * DIM + d4);
            float4 ok; ok.x = kk.x + pk.x; ok.y = kk.y + pk.y; ok.z = kk.z + pk.z; ok.w = kk.w + pk.w;
            float4 ov; ov.x = vv.x + pv.x; ov.y = vv.y + pv.y; ov.z = vv.z + pv.z; ov.w = vv.w + pv.w;
            *(float4*)(xk + tt * 4096 + l * DIM + d4) = ok;
            *(float4*)(xv + tt * 4096 + l * DIM + d4) = ov;
        }
    }
    __syncthreads();

    float ak[2] = {0.f, 0.f};
    float av[2] = {0.f, 0.f};
    const int i0 = seg * 256;
#pragma unroll 4
    for (int i = i0; i < i0 + 256; ++i) {
        float wk = Wk[i * DIM + e];
        float wv = Wv[i * DIM + e];
#pragma unroll
        for (int tt = 0; tt < 2; ++tt) {
            ak[tt] += xk[tt * 4096 + i] * wk;
            av[tt] += xv[tt * 4096 + i] * wv;
        }
    }
#pragma unroll
    for (int tt = 0; tt < 2; ++tt) {
        red[((0 * 16 + seg) * 2 + tt) * 32 + lane] = ak[tt];
        red[((1 * 16 + seg) * 2 + tt) * 32 + lane] = av[tt];
    }
    __syncthreads();

    if (tid < 128) {
        int b  = tid >> 6;
        int tt = (tid >> 5) & 1;
        int ee = tid & 31;
        int t  = t0 + tt;
        if (t < Tc) {
            float sv = 0.f;
#pragma unroll
            for (int sg = 0; sg < 16; ++sg)
                sv += red[((b * 16 + sg) * 2 + tt) * 32 + ee];
            if (b == 0) g_ck[(t * HKV + h) * DIM + e0 + ee] = sv + bk[e0 + ee];
            else        g_cv[(t * HKV + h) * DIM + e0 + ee] = sv + bv[e0 + ee];
        }
    }
}

// =====================================================================
// Kernel B: compressed attention + pooled top-k selection
// grid (S, HKV), block 256 (8 warps = 8 heads of the GQA group)
// =====================================================================
__global__ __launch_bounds__(256, 4)
void cmpattn_kernel(const float* __restrict__ q, int S, int Tc)
{
    __shared__ float qs[8][DIM];
    __shared__ float cl[8][96];
    __shared__ float sc[96];
    __shared__ float pooled[NKBLK];

    const int s    = blockIdx.x;
    const int hkv  = blockIdx.y;
    const int tid  = threadIdx.x;
    const int g    = tid >> 5;
    const int lane = tid & 31;

    for (int i = tid; i < 8 * DIM; i += 256) {
        int gg = i >> 7, d = i & 127;
        qs[gg][d] = q[(s * HQ + hkv * 8 + gg) * DIM + d];
    }
    __syncthreads();

    int tvis = (s >= 31) ? ((s - 31) / 16 + 1) : 0;
    if (tvis > Tc) tvis = Tc;

    float q0 = qs[g][lane], q1 = qs[g][lane + 32];
    float q2 = qs[g][lane + 64], q3 = qs[g][lane + 96];

    for (int t = 0; t < tvis; ++t) {
        const float* ckp = &g_ck[(t * HKV + hkv) * DIM];
        float p = q0 * ckp[lane] + q1 * ckp[lane + 32] +
                  q2 * ckp[lane + 64] + q3 * ckp[lane + 96];
#pragma unroll
        for (int o = 16; o; o >>= 1) p += __shfl_xor_sync(0xffffffffu, p, o);
        if (lane == 0) cl[g][t] = p * SCALE;
    }
    __syncwarp();

    // softmax over t < tvis (no max-subtraction needed: |logit| < ~10)
    float ssum = 0.f;
    for (int t = lane; t < tvis; t += 32) { float e_ = __expf(cl[g][t]); cl[g][t] = e_; ssum += e_; }
#pragma unroll
    for (int o = 16; o; o >>= 1) ssum += __shfl_xor_sync(0xffffffffu, ssum, o);
    float inv = 1.0f / fmaxf(ssum, 1e-9f);
    for (int t = lane; t < tvis; t += 32) cl[g][t] *= inv;
    for (int t = tvis + lane; t < 96; t += 32) cl[g][t] = 0.f;
    __syncwarp();

    // compressed-branch output
    float a0 = 0.f, a1 = 0.f, a2 = 0.f, a3 = 0.f;
    for (int t = 0; t < tvis; ++t) {
        float p = cl[g][t];
        const float* cvp = &g_cv[(t * HKV + hkv) * DIM];
        a0 += p * cvp[lane];      a1 += p * cvp[lane + 32];
        a2 += p * cvp[lane + 64]; a3 += p * cvp[lane + 96];
    }
    float* outp = &g_cmp[(s * HQ + hkv * 8 + g) * DIM];
    outp[lane] = a0; outp[lane + 32] = a1; outp[lane + 64] = a2; outp[lane + 96] = a3;
    __syncthreads();

    // GQA-summed score
    for (int t = tid; t < Tc; t += 256) {
        float sv = 0.f;
#pragma unroll
        for (int gg = 0; gg < 8; ++gg) sv += cl[gg][t];
        sc[t] = sv;
    }
    __syncthreads();

    // avg-pool (kernel 5, stride 4, ceil_mode, count-include-pad w/ P=0)
    if (tid < NKBLK) {
        float sum = 0.f; int cnt = 0;
#pragma unroll
        for (int j = 0; j < 5; ++j) {
            int idx = tid * 4 + j;
            if (idx < Tc) { sum += sc[idx]; cnt++; }
        }
        pooled[tid] = sum / (float)cnt;
    }
    __syncthreads();

    // top-16 of 24 with jax tie rule (lower index wins)
    if (tid < 32) {
        unsigned selbit = 0;
        if (tid < NKBLK) {
            float vme = pooled[tid];
            int rank = 0;
#pragma unroll
            for (int o = 0; o < NKBLK; ++o) {
                float vo = pooled[o];
                if (vo > vme || (vo == vme && o < tid)) rank++;
            }
            selbit = (rank < 16) ? 1u : 0u;
        }
        unsigned msk = __ballot_sync(0xffffffffu, selbit);
        if (tid == 0) g_sel[hkv * S + s] = msk;
    }
}

// Fast-path AV: one stream, float4 V loads (lane owns dims 4*lane..4*lane+3).
#define AV_FAST(ACC)                                                        \
    for (int u = 0; u < 32; ++u) {                                          \
        float4 v4 = *(const float4*)(vs + u * KPAD + 4 * lane);             \
        _Pragma("unroll")                                                   \
        for (int j = 0; j < 4; ++j) {                                       \
            float p = ps[(w * 8 + j) * 32 + u];                             \
            ACC[j].x += p * v4.x; ACC[j].y += p * v4.y;                     \
            ACC[j].z += p * v4.z; ACC[j].w += p * v4.w;                     \
        }                                                                   \
    }

// =====================================================================
// Kernel C: block-sparse + sliding-window attention, gated combine.
// R9 + : single barrier per tile (fill-after-barrier is WAR-safe),
// flat-grid true LPT ordering, float4 AV accumulators / epilogue.
// grid ((S/64)*HQ), block 512
// =====================================================================
__global__ __launch_bounds__(512, 1)
void mainattn_kernel(const float* __restrict__ q, const float* __restrict__ k,
                     const float* __restrict__ v, const float* __restrict__ Wg,
                     const float* __restrict__ bg, float* __restrict__ out, int S)
{
    extern __shared__ float sm[];
    float*    qs   = sm;                       // 64*128
    float*    ksb  = qs + 64 * DIM;            // 2 x 32*KPAD
    float*    vsb  = ksb + 2 * TILEF;          // 2 x 32*KPAD
    float*    ps   = vsb + 2 * TILEF;          // 16*8*32
    unsigned* selm = (unsigned*)(ps + 16 * 8 * 32);   // 64 + 1(union)

    // true LPT: heaviest qtiles (all heads) first
    const int nqt   = gridDim.x / HQ;
    const int qtile = (nqt - 1) - (blockIdx.x / HQ);
    const int h     = blockIdx.x % HQ;
    const int hkv   = h >> 3;
    const int qbase = qtile * 64;
    const int tid   = threadIdx.x;
    const int w     = tid >> 5;
    const int lane  = tid & 31;

    // vectorized Q fill: 64*128 floats = 2048 float4
    for (int f = tid; f < 2048; f += 512) {
        int ql = f >> 5, d4 = (f & 31) << 2;
        *(float4*)(qs + ql * DIM + d4) =
            *(const float4*)(q + ((qbase + ql) * HQ + h) * DIM + d4);
    }
    if (tid < 64) selm[tid] = g_sel[hkv * S + qbase + tid];
    __syncthreads();
    if (tid == 0) {
        unsigned u = 0;
#pragma unroll 8
        for (int i = 0; i < 64; ++i) u |= selm[i];
        selm[64] = u;
    }
    __syncthreads();
    const unsigned unionmask = selm[64];

    int sj[4];
#pragma unroll
    for (int j = 0; j < 4; ++j) sj[j] = qbase + w * 4 + j;
    const int wlo0 = sj[0] - (WIN - 1);
    const int wlo3 = sj[3] - (WIN - 1);
    const int winloCTA = qbase - (WIN - 1);

    float sumS[4], sumW[4];
    float4 accC[4], accSo[4], accWo[4];
#pragma unroll
    for (int j = 0; j < 4; ++j) {
        sumS[j] = 0.f; sumW[j] = 0.f;
        accC[j]  = make_float4(0.f, 0.f, 0.f, 0.f);
        accSo[j] = make_float4(0.f, 0.f, 0.f, 0.f);
        accWo[j] = make_float4(0.f, 0.f, 0.f, 0.f);
    }

    const int nkt = (qbase + 64) >> 5;

    // prefetch cursor over *needed* tiles only
    int cur = -1;
    for (int t = 0; t < nkt; ++t) {
        int u0t = t << 5;
        if (((unionmask >> (u0t >> 6)) & 1u) || (u0t + 31 >= winloCTA)) { cur = t; break; }
    }
    int buf = 0;
    if (cur >= 0) {
        const int u0 = cur << 5;
        for (int f = tid; f < 1024; f += 512) {
            int u = f >> 5, d4 = (f & 31) << 2;
            int gk = ((u0 + u) * HKV + hkv) * DIM + d4;
            cp16(ksb + u * KPAD + d4, k + gk);
            cp16(vsb + u * KPAD + d4, v + gk);
        }
        asm volatile("cp.async.commit_group;" ::: "memory");
    }

    while (cur >= 0) {
        int nxt = -1;
        for (int t = cur + 1; t < nkt; ++t) {
            int u0t = t << 5;
            if (((unionmask >> (u0t >> 6)) & 1u) || (u0t + 31 >= winloCTA)) { nxt = t; break; }
        }
        asm volatile("cp.async.wait_group 0;" ::: "memory");
        __syncthreads();   // (1) cur tile visible to all; (2) all threads done
                           //     with previous tile's compute -> filling the
                           //     old buffer below is WAR-safe. Single barrier.

        if (nxt >= 0) {    // overlap next fill with compute (writes buf^1)
            const int u0n = nxt << 5;
            float* kd = ksb + (buf ^ 1) * TILEF;
            float* vd = vsb + (buf ^ 1) * TILEF;
            for (int f = tid; f < 1024; f += 512) {
                int u = f >> 5, d4 = (f & 31) << 2;
                int gk = ((u0n + u) * HKV + hkv) * DIM + d4;
                cp16(kd + u * KPAD + d4, k + gk);
                cp16(vd + u * KPAD + d4, v + gk);
            }
            asm volatile("cp.async.commit_group;" ::: "memory");
        }

        const float* ks = ksb + buf * TILEF;
        const float* vs = vsb + buf * TILEF;
        const int u0 = cur << 5;

        if (u0 <= sj[3]) {
            const int kb = u0 >> 6;
            bool sq[4];
#pragma unroll
            for (int j = 0; j < 4; ++j) sq[j] = (selm[w * 4 + j] >> kb) & 1u;
            const bool selAll  = sq[0] && sq[1] && sq[2] && sq[3];
            const bool selAny  = sq[0] || sq[1] || sq[2] || sq[3];
            const bool causalAll  = (u0 + 31 <= sj[0]);
            const bool fullWinAll = (u0 >= wlo3);
            const bool noWinAll   = (u0 + 31 < wlo0);

            int mode;
            if (causalAll && selAll && fullWinAll)       mode = 0;   // BOTH
            else if (causalAll && selAll && noWinAll)    mode = 1;   // SEL
            else if (causalAll && !selAny && fullWinAll) mode = 2;   // WIN
            else if (causalAll && !selAny && noWinAll)   mode = -1;  // nothing
            else                                         mode = 3;   // fallback

            bool needS[4], needW[4], needA[4];
            if (mode == 3) {
                bool any = false;
#pragma unroll
                for (int j = 0; j < 4; ++j) {
                    bool act = (u0 <= sj[j]);
                    needS[j] = act && sq[j];
                    needW[j] = act && (u0 + 31 >= sj[j] - (WIN - 1));
                    needA[j] = needS[j] || needW[j];
                    any |= needA[j];
                }
                if (!any) mode = -1;
            }

            if (mode >= 0) {
                // ---- QK (shared by all modes) ----
                const float4* k4 = (const float4*)(ks + lane * KPAD);
                float lg[4] = {0.f, 0.f, 0.f, 0.f};
#pragma unroll 8
                for (int c = 0; c < 32; ++c) {
                    float4 kv4 = k4[c];
#pragma unroll
                    for (int j = 0; j < 4; ++j) {
                        float4 q4 = *(const float4*)(qs + (w * 4 + j) * DIM + 4 * c);
                        lg[j] += q4.x * kv4.x + q4.y * kv4.y + q4.z * kv4.z + q4.w * kv4.w;
                    }
                }

                if (mode == 0) {          // BOTH
#pragma unroll
                    for (int j = 0; j < 4; ++j) {
                        float e = __expf(lg[j] * SCALE);
                        ps[(w * 8 + j) * 32 + lane] = e;
                        sumS[j] += e; sumW[j] += e;
                    }
                    __syncwarp();
                    AV_FAST(accC)
                    __syncwarp();
                } else if (mode == 1) {   // SEL only
#pragma unroll
                    for (int j = 0; j < 4; ++j) {
                        float e = __expf(lg[j] * SCALE);
                        ps[(w * 8 + j) * 32 + lane] = e;
                        sumS[j] += e;
                    }
                    __syncwarp();
                    AV_FAST(accSo)
                    __syncwarp();
                } else if (mode == 2) {   // WIN only
#pragma unroll
                    for (int j = 0; j < 4; ++j) {
                        float e = __expf(lg[j] * SCALE);
                        ps[(w * 8 + j) * 32 + lane] = e;
                        sumW[j] += e;
                    }
                    __syncwarp();
                    AV_FAST(accWo)
                    __syncwarp();
                } else {                  // fallback: generic two-stream
                    const int ku = u0 + lane;
#pragma unroll
                    for (int j = 0; j < 4; ++j) {
                        if (!needA[j]) continue;
                        bool causal = (ku <= sj[j]);
                        bool mS = causal && needS[j];
                        bool mW = causal && needW[j] && (ku >= sj[j] - (WIN - 1));
                        float e = (mS || mW) ? __expf(lg[j] * SCALE) : 0.f;
                        if (needS[j]) {
                            float pS = mS ? e : 0.f;
                            sumS[j] += pS;
                            ps[(w * 8 + j * 2 + 0) * 32 + lane] = pS;
                        }
                        if (needW[j]) {
                            float pW = mW ? e : 0.f;
                            sumW[j] += pW;
                            ps[(w * 8 + j * 2 + 1) * 32 + lane] = pW;
                        }
                    }
                    __syncwarp();
                    for (int u = 0; u < 32; ++u) {
                        float4 v4 = *(const float4*)(vs + u * KPAD + 4 * lane);
#pragma unroll
                        for (int j = 0; j < 4; ++j) {
                            if (needS[j]) {
                                float pS = ps[(w * 8 + j * 2 + 0) * 32 + u];
                                accSo[j].x += pS * v4.x; accSo[j].y += pS * v4.y;
                                accSo[j].z += pS * v4.z; accSo[j].w += pS * v4.w;
                            }
                            if (needW[j]) {
                                float pW = ps[(w * 8 + j * 2 + 1) * 32 + u];
                                accWo[j].x += pW * v4.x; accWo[j].y += pW * v4.y;
                                accWo[j].z += pW * v4.z; accWo[j].w += pW * v4.w;
                            }
                        }
                    }
                    __syncwarp();
                }
            }
        }

        cur = nxt; buf ^= 1;
    }

    // epilogue: reduce denominators once, gate + combine (float4, d=4*lane+*)
#pragma unroll
    for (int j = 0; j < 4; ++j) {
        const int s = sj[j];
        float rs = sumS[j], rw = sumW[j];
#pragma unroll
        for (int o = 16; o; o >>= 1) {
            rs += __shfl_xor_sync(0xffffffffu, rs, o);
            rw += __shfl_xor_sync(0xffffffffu, rw, o);
        }
        float invS = 1.0f / fmaxf(rs, 1e-9f);
        float invW = 1.0f / fmaxf(rw, 1e-9f);

        const float* qrow = qs + (w * 4 + j) * DIM;
        float4 q4 = *(const float4*)(qrow + 4 * lane);
        float g0 = q4.x * Wg[(4 * lane + 0) * 3 + 0] + q4.y * Wg[(4 * lane + 1) * 3 + 0]
                 + q4.z * Wg[(4 * lane + 2) * 3 + 0] + q4.w * Wg[(4 * lane + 3) * 3 + 0];
        float g1 = q4.x * Wg[(4 * lane + 0) * 3 + 1] + q4.y * Wg[(4 * lane + 1) * 3 + 1]
                 + q4.z * Wg[(4 * lane + 2) * 3 + 1] + q4.w * Wg[(4 * lane + 3) * 3 + 1];
        float g2 = q4.x * Wg[(4 * lane + 0) * 3 + 2] + q4.y * Wg[(4 * lane + 1) * 3 + 2]
                 + q4.z * Wg[(4 * lane + 2) * 3 + 2] + q4.w * Wg[(4 * lane + 3) * 3 + 2];
#pragma unroll
        for (int o = 16; o; o >>= 1) {
            g0 += __shfl_xor_sync(0xffffffffu, g0, o);
            g1 += __shfl_xor_sync(0xffffffffu, g1, o);
            g2 += __shfl_xor_sync(0xffffffffu, g2, o);
        }
        g0 = 1.0f / (1.0f + __expf(-(g0 + bg[0])));
        g1 = 1.0f / (1.0f + __expf(-(g1 + bg[1])));
        g2 = 1.0f / (1.0f + __expf(-(g2 + bg[2])));

        const float4 cm4 = *(const float4*)(&g_cmp[(s * HQ + h) * DIM] + 4 * lane);
        float4 o4;
        o4.x = g0 * ((accC[j].x + accSo[j].x) * invS) + g1 * ((accC[j].x + accWo[j].x) * invW) + g2 * cm4.x;
        o4.y = g0 * ((accC[j].y + accSo[j].y) * invS) + g1 * ((accC[j].y + accWo[j].y) * invW) + g2 * cm4.y;
        o4.z = g0 * ((accC[j].z + accSo[j].z) * invS) + g1 * ((accC[j].z + accWo[j].z) * invW) + g2 * cm4.z;
        o4.w = g0 * ((accC[j].w + accSo[j].w) * invS) + g1 * ((accC[j].w + accWo[j].w) * invW) + g2 * cm4.w;
        *(float4*)(out + (s * HQ + h) * DIM + 4 * lane) = o4;
    }
}

// =====================================================================
extern "C" void kernel_launch(void* const* d_in, const int* in_sizes, int n_in,
                              void* d_out, int out_size)
{
    const float* q   = (const float*)d_in[0];
    const float* k   = (const float*)d_in[1];
    const float* v   = (const float*)d_in[2];
    const float* Wk  = (const float*)d_in[3];
    const float* bk  = (const float*)d_in[4];
    const float* Wv  = (const float*)d_in[5];
    const float* bv  = (const float*)d_in[6];
    const float* pek = (const float*)d_in[7];
    const float* pev = (const float*)d_in[8];
    const float* Wg  = (const float*)d_in[9];
    const float* bg  = (const float*)d_in[10];
    float* out = (float*)d_out;

    const int S  = in_sizes[0] / (HQ * DIM);
    const int Tc = (S - 32) / 16 + 1;

    const int smemA = (4 * 4096 + 2 * 16 * 2 * 32) * (int)sizeof(float);   // 73728
    const int smemC = (64 * DIM + 4 * TILEF + 16 * 8 * 32) * (int)sizeof(float)
                      + 72 * (int)sizeof(unsigned);                        // ~117 KB

    cudaFuncSetAttribute(compress_kernel, cudaFuncAttributeMaxDynamicSharedMemorySize, smemA);
    cudaFuncSetAttribute(mainattn_kernel, cudaFuncAttributeMaxDynamicSharedMemorySize, smemC);

    dim3 gA((Tc + 1) / 2, HKV, 4);
    compress_kernel<<<gA, 512, smemA>>>(k, v, Wk, bk, Wv, bv, pek, pev, S, Tc);

    dim3 gB(S, HKV);
    cmpattn_kernel<<<gB, 256>>>(q, S, Tc);

    mainattn_kernel<<<(S / 64) * HQ, 512, smemC>>>(q, k, v, Wg, bg, out, S);
}